// round 5
// baseline (speedup 1.0000x reference)
#include <cuda_runtime.h>

#define BATCH 65536
#define NP 2048
#define RPB 16                     /* rows per block */
#define NBLK (BATCH / RPB)         /* 4096 */
#define NT 160                     /* 5 warps; 146 active j-threads */
#define NJ2 146                    /* j pairs per row (292 j / 2) */
#define INV_SQRT2F 0.70710678118654752440f

// Per-block partial sums: [blk*8 + comp]
// 0..3 : SumA, SumBr, SumBi, SumC    4..7 : sum(c_r), sum(c_r^2), sum(c_i), sum(c_i^2)
__device__ float g_partials[NBLK * 8];
__device__ int   g_count = 0;

#define LOADROW(B0,B1,B2,B3,B4,B5,B6, r)                          \
    {                                                             \
        const float2* rp_ = base + (size_t)(r) * (NP/2);          \
        B0 = rp_[  1 + off];  B1 = rp_[147 + off];                \
        B2 = rp_[293 + off];  B3 = rp_[439 + off];                \
        B4 = rp_[585 + off];  B5 = rp_[731 + off];                \
        B6 = rp_[877 + off];                                      \
    }

#define COMPUTE(B0,B1,B2,B3,B4,B5,B6, r)                          \
    {                                                             \
        const float bb  = scoef[(r)*5 + 0];                       \
        const float arc = scoef[(r)*5 + 1];                       \
        const float aic = scoef[(r)*5 + 2];                       \
        const float brc = scoef[(r)*5 + 3];                       \
        const float bic = scoef[(r)*5 + 4];                       \
        {   /* lane 0 */                                          \
            float S  = B0.x + B1.x + B2.x + B4.x + B5.x + B6.x;   \
            float ar = fmaf(arc, B3.x, brc);                      \
            float ai = fmaf(aic, B3.x, bic);                      \
            float bS = bb * S;                                    \
            float p  = p2.x;                                      \
            sA  = fmaf(p, fmaf(ar, ar, ai * ai), sA);             \
            sBr = fmaf(p, ar * bS, sBr);                          \
            sBi = fmaf(p, ai * bS, sBi);                          \
            sC  = fmaf(p, bS * bS, sC);                           \
        }                                                         \
        {   /* lane 1 */                                          \
            float S  = B0.y + B1.y + B2.y + B4.y + B5.y + B6.y;   \
            float ar = fmaf(arc, B3.y, brc);                      \
            float ai = fmaf(aic, B3.y, bic);                      \
            float bS = bb * S;                                    \
            float p  = p2.y;                                      \
            sA  = fmaf(p, fmaf(ar, ar, ai * ai), sA);             \
            sBr = fmaf(p, ar * bS, sBr);                          \
            sBi = fmaf(p, ai * bS, sBi);                          \
            sC  = fmaf(p, bS * bS, sC);                           \
        }                                                         \
    }

__global__ __launch_bounds__(NT) void isi_fused_kernel(
    const float* __restrict__ dnn,
    const float* __restrict__ bv,
    const float* __restrict__ hv,
    const float* __restrict__ xr,
    const float* __restrict__ xi,
    const float* __restrict__ isr,   // ISI_symbols_real (B,6)
    const float* __restrict__ isi,   // ISI_symbols_imag (B,6)
    const float* __restrict__ ich,   // ISI_channels     (B,6)
    const float* __restrict__ noise,
    const float* __restrict__ prob,
    float* __restrict__ out)
{
    const int tid  = threadIdx.x;
    const int blk  = blockIdx.x;
    const int row0 = blk * RPB;
    const bool act = (tid < NJ2);
    const int off  = act ? tid : (NJ2 - 1);   // clamped: always in-bounds

    __shared__ float scoef[RPB * 5];          // bb, ar_c, ai_c, br_c, bi_c per row

    float sA = 0.f, sBr = 0.f, sBi = 0.f, sC = 0.f;
    float sM1r = 0.f, sM2r = 0.f, sM1i = 0.f, sM2i = 0.f;

    // prob pair for this thread's two j (zeroed for inactive lanes -> all
    // four accumulators scale by p, so clamped duplicate loads contribute 0)
    float2 p2 = make_float2(0.f, 0.f);
    if (act) p2 = ((const float2*)prob)[439 + tid];

    // Precompute per-row coefficients + moment terms (threads 0..RPB-1)
    if (tid < RPB) {
        const int r = row0 + tid;
        const float bb  = bv[r];
        const float bh  = bb * hv[r];
        const float xrr = xr[r];
        const float xii = xi[r];
        const float nz  = INV_SQRT2F * noise[r];
        scoef[tid * 5 + 0] = bb;
        scoef[tid * 5 + 1] = bh * xrr;
        scoef[tid * 5 + 2] = bh * xii;
        scoef[tid * 5 + 3] = nz - xrr;
        scoef[tid * 5 + 4] = nz - xii;

        const float c  = ich[(size_t)r * 6];
        const float cr = c * isr[(size_t)r * 6];
        const float ci = c * isi[(size_t)r * 6];
        sM1r = cr; sM2r = cr * cr;
        sM1i = ci; sM2i = ci * ci;
    }
    __syncthreads();

    const float2* base = (const float2*)(dnn + (size_t)row0 * NP);
    float2 A0, A1, A2, A3, A4, A5, A6;
    float2 B0, B1, B2, B3, B4, B5, B6;

    // Register double-buffered streaming: load row r+1 while computing row r.
    LOADROW(A0,A1,A2,A3,A4,A5,A6, 0);
    #pragma unroll
    for (int r = 0; r < RPB; r += 2) {
        LOADROW(B0,B1,B2,B3,B4,B5,B6, r + 1);
        COMPUTE(A0,A1,A2,A3,A4,A5,A6, r);
        if (r + 2 < RPB) LOADROW(A0,A1,A2,A3,A4,A5,A6, r + 2);
        COMPUTE(B0,B1,B2,B3,B4,B5,B6, r + 1);
    }

    // Block reduction: warp shuffle then across 5 warps via smem
    __shared__ float sred[5 * 8];
    const unsigned FULL = 0xFFFFFFFFu;
    #pragma unroll
    for (int o = 16; o > 0; o >>= 1) {
        sA   += __shfl_down_sync(FULL, sA, o);
        sBr  += __shfl_down_sync(FULL, sBr, o);
        sBi  += __shfl_down_sync(FULL, sBi, o);
        sC   += __shfl_down_sync(FULL, sC, o);
        sM1r += __shfl_down_sync(FULL, sM1r, o);
        sM2r += __shfl_down_sync(FULL, sM2r, o);
        sM1i += __shfl_down_sync(FULL, sM1i, o);
        sM2i += __shfl_down_sync(FULL, sM2i, o);
    }
    const int warp = tid >> 5, lane = tid & 31;
    if (lane == 0) {
        sred[warp * 8 + 0] = sA;   sred[warp * 8 + 1] = sBr;
        sred[warp * 8 + 2] = sBi;  sred[warp * 8 + 3] = sC;
        sred[warp * 8 + 4] = sM1r; sred[warp * 8 + 5] = sM2r;
        sred[warp * 8 + 6] = sM1i; sred[warp * 8 + 7] = sM2i;
    }
    __syncthreads();
    if (tid < 8) {
        float acc = sred[tid] + sred[8 + tid] + sred[16 + tid]
                  + sred[24 + tid] + sred[32 + tid];
        g_partials[blk * 8 + tid] = acc;
    }

    // ---- last-block final combine (deterministic: fixed summation order) ----
    __shared__ int s_last;
    __threadfence();
    __syncthreads();
    if (tid == 0)
        s_last = (atomicAdd(&g_count, 1) == NBLK - 1);
    __syncthreads();
    if (!s_last) return;

    __threadfence();  // acquire: all blocks' partials visible

    __shared__ double dsm[8 * NT];
    double acc[8];
    #pragma unroll
    for (int c = 0; c < 8; ++c) acc[c] = 0.0;
    for (int b = tid; b < NBLK; b += NT) {
        #pragma unroll
        for (int c = 0; c < 8; ++c)
            acc[c] += (double)g_partials[b * 8 + c];
    }
    #pragma unroll
    for (int c = 0; c < 8; ++c) dsm[c * NT + tid] = acc[c];
    __syncthreads();

    if (tid < 8) {
        double s = 0.0;
        for (int i = 0; i < NT; ++i) s += dsm[tid * NT + i];
        dsm[tid] = s;
    }
    __syncthreads();
    if (tid == 0) {
        const double invB = 1.0 / (double)BATCH;
        double SumA  = dsm[0], SumBr = dsm[1], SumBi = dsm[2], SumC = dsm[3];
        double m1r = dsm[4] * invB, m2r = dsm[5] * invB;
        double m1i = dsm[6] * invB, m2i = dsm[7] * invB;
        out[0] = (float)((SumA + 2.0 * m1r * SumBr + 2.0 * m1i * SumBi
                          + (m2r + m2i) * SumC) * invB);
        g_count = 0;   // self-reset for next graph replay
    }
}

extern "C" void kernel_launch(void* const* d_in, const int* in_sizes, int n_in,
                              void* d_out, int out_size)
{
    const float* dnn   = (const float*)d_in[0];
    const float* bv    = (const float*)d_in[1];
    const float* hv    = (const float*)d_in[2];
    const float* xr    = (const float*)d_in[3];
    const float* xi    = (const float*)d_in[4];
    const float* isr   = (const float*)d_in[5];
    const float* isi   = (const float*)d_in[6];
    const float* ich   = (const float*)d_in[7];
    const float* noise = (const float*)d_in[8];
    const float* prob  = (const float*)d_in[9];

    isi_fused_kernel<<<NBLK, NT>>>(dnn, bv, hv, xr, xi, isr, isi, ich,
                                   noise, prob, (float*)d_out);
}

// round 10
// speedup vs baseline: 1.0934x; 1.0934x over previous
#include <cuda_runtime.h>

#define BATCH 65536
#define NP 2048
#define RPB 16                     /* rows per block */
#define NBLK (BATCH / RPB)         /* 4096 */
#define NT 160                     /* 2 groups of 80 threads; 74 active each */
#define INV_SQRT2F 0.70710678118654752440f

// Per-block partial sums: [blk*8 + comp]
// 0..3 : SumA, SumBr, SumBi, SumC    4..7 : sum(c_r), sum(c_r^2), sum(c_i), sum(c_i^2)
__device__ float g_partials[NBLK * 8];
__device__ int   g_count = 0;

// Stream offsets in float4 units within a row (cols {2,294,586,878,1170,1462,1754}+j,
// j = 4t-2+e  ->  float4 index = {0,73,146,219,292,365,438} + t). Stream 3 is d0.
#define LOAD7(P, rp)                                   \
    {                                                  \
        P##0 = (rp)[0];    P##1 = (rp)[73];            \
        P##2 = (rp)[146];  P##3 = (rp)[219];           \
        P##4 = (rp)[292];  P##5 = (rp)[365];           \
        P##6 = (rp)[438];                              \
    }

#define LANE(P, e, pw)                                                   \
    {                                                                    \
        float S  = (P##0).e + (P##1).e + (P##2).e                        \
                 + (P##4).e + (P##5).e + (P##6).e;                       \
        float ar = fmaf(arc, (P##3).e, brc);                             \
        float ai = fmaf(aic, (P##3).e, bic);                             \
        float bS = bb * S;                                               \
        sA  = fmaf(pw, fmaf(ar, ar, ai * ai), sA);                       \
        sBr = fmaf(pw, ar * bS, sBr);                                    \
        sBi = fmaf(pw, ai * bS, sBi);                                    \
        sC  = fmaf(pw, bS * bS, sC);                                     \
    }

#define COMPUTE7(P, ridx)                                           \
    {                                                               \
        const float bb  = scoef[(ridx) * 5 + 0];                    \
        const float arc = scoef[(ridx) * 5 + 1];                    \
        const float aic = scoef[(ridx) * 5 + 2];                    \
        const float brc = scoef[(ridx) * 5 + 3];                    \
        const float bic = scoef[(ridx) * 5 + 4];                    \
        LANE(P, x, p4.x) LANE(P, y, p4.y)                           \
        LANE(P, z, p4.z) LANE(P, w, p4.w)                           \
    }

__global__ __launch_bounds__(NT, 4) void isi_fused_kernel(
    const float* __restrict__ dnn,
    const float* __restrict__ bv,
    const float* __restrict__ hv,
    const float* __restrict__ xr,
    const float* __restrict__ xi,
    const float* __restrict__ isr,   // ISI_symbols_real (B,6)
    const float* __restrict__ isi,   // ISI_symbols_imag (B,6)
    const float* __restrict__ ich,   // ISI_channels     (B,6)
    const float* __restrict__ noise,
    const float* __restrict__ prob,
    float* __restrict__ out)
{
    const int tid  = threadIdx.x;
    const int blk  = blockIdx.x;
    const int row0 = blk * RPB;
    const int g    = tid / 80;              // row-group 0/1
    const int s    = tid % 80;              // slot within group
    const int t    = (s < 74) ? s : 73;     // clamped j-slot (always in-bounds)

    __shared__ float scoef[RPB * 5];        // bb, ar_c, ai_c, br_c, bi_c per row

    float sA = 0.f, sBr = 0.f, sBi = 0.f, sC = 0.f;
    float sM1r = 0.f, sM2r = 0.f, sM1i = 0.f, sM2i = 0.f;

    // prob float4: cols 876+4t .. 879+4t  == p[878 + j], j = 4t-2+e.
    // Zero invalid lanes (edge j outside [0,292)) and inactive threads.
    float4 p4 = __ldg((const float4*)prob + 219 + t);
    if (s >= 74) { p4.x = 0.f; p4.y = 0.f; p4.z = 0.f; p4.w = 0.f; }
    if (t == 0)  { p4.x = 0.f; p4.y = 0.f; }
    if (t == 73) { p4.z = 0.f; p4.w = 0.f; }

    // Per-row coefficients + moment terms (threads 0..RPB-1)
    if (tid < RPB) {
        const int r = row0 + tid;
        const float bb  = bv[r];
        const float bh  = bb * hv[r];
        const float xrr = xr[r];
        const float xii = xi[r];
        const float nz  = INV_SQRT2F * noise[r];
        scoef[tid * 5 + 0] = bb;
        scoef[tid * 5 + 1] = bh * xrr;
        scoef[tid * 5 + 2] = bh * xii;
        scoef[tid * 5 + 3] = nz - xrr;
        scoef[tid * 5 + 4] = nz - xii;

        const float c  = ich[(size_t)r * 6];
        const float cr = c * isr[(size_t)r * 6];
        const float ci = c * isi[(size_t)r * 6];
        sM1r = cr; sM2r = cr * cr;
        sM1i = ci; sM2i = ci * ci;
    }
    __syncthreads();

    // Each thread streams rows {g, g+2, ..., g+14} of this block with an
    // explicit register double buffer (7 float4 per row in flight, 2 rows deep).
    const float4* rp = (const float4*)dnn + (size_t)(row0 + g) * (NP / 4) + t;
    const int RSTRIDE = 2 * (NP / 4);       // advance 2 rows per step

    float4 A0, A1, A2, A3, A4, A5, A6;
    float4 B0, B1, B2, B3, B4, B5, B6;

    LOAD7(A, rp); rp += RSTRIDE;
    #pragma unroll
    for (int i = 0; i < RPB / 2; i += 2) {
        LOAD7(B, rp); rp += RSTRIDE;
        COMPUTE7(A, 2 * i + g);
        if (i + 2 < RPB / 2) { LOAD7(A, rp); rp += RSTRIDE; }
        COMPUTE7(B, 2 * (i + 1) + g);
    }

    // Block reduction: warp shuffle then across 5 warps via smem
    __shared__ float sred[5 * 8];
    const unsigned FULL = 0xFFFFFFFFu;
    #pragma unroll
    for (int o = 16; o > 0; o >>= 1) {
        sA   += __shfl_down_sync(FULL, sA, o);
        sBr  += __shfl_down_sync(FULL, sBr, o);
        sBi  += __shfl_down_sync(FULL, sBi, o);
        sC   += __shfl_down_sync(FULL, sC, o);
        sM1r += __shfl_down_sync(FULL, sM1r, o);
        sM2r += __shfl_down_sync(FULL, sM2r, o);
        sM1i += __shfl_down_sync(FULL, sM1i, o);
        sM2i += __shfl_down_sync(FULL, sM2i, o);
    }
    const int warp = tid >> 5, lane = tid & 31;
    if (lane == 0) {
        sred[warp * 8 + 0] = sA;   sred[warp * 8 + 1] = sBr;
        sred[warp * 8 + 2] = sBi;  sred[warp * 8 + 3] = sC;
        sred[warp * 8 + 4] = sM1r; sred[warp * 8 + 5] = sM2r;
        sred[warp * 8 + 6] = sM1i; sred[warp * 8 + 7] = sM2i;
    }
    __syncthreads();
    if (tid < 8) {
        float acc = sred[tid] + sred[8 + tid] + sred[16 + tid]
                  + sred[24 + tid] + sred[32 + tid];
        g_partials[blk * 8 + tid] = acc;
    }

    // ---- last-block final combine (deterministic: fixed summation order) ----
    __shared__ int s_last;
    __threadfence();
    __syncthreads();
    if (tid == 0)
        s_last = (atomicAdd(&g_count, 1) == NBLK - 1);
    __syncthreads();
    if (!s_last) return;

    __threadfence();  // acquire: all blocks' partials visible

    __shared__ double dsm[8 * NT];
    double acc[8];
    #pragma unroll
    for (int c = 0; c < 8; ++c) acc[c] = 0.0;
    for (int b = tid; b < NBLK; b += NT) {
        #pragma unroll
        for (int c = 0; c < 8; ++c)
            acc[c] += (double)g_partials[b * 8 + c];
    }
    #pragma unroll
    for (int c = 0; c < 8; ++c) dsm[c * NT + tid] = acc[c];
    __syncthreads();

    if (tid < 8) {
        double sum = 0.0;
        for (int i = 0; i < NT; ++i) sum += dsm[tid * NT + i];
        dsm[tid] = sum;
    }
    __syncthreads();
    if (tid == 0) {
        const double invB = 1.0 / (double)BATCH;
        double SumA  = dsm[0], SumBr = dsm[1], SumBi = dsm[2], SumC = dsm[3];
        double m1r = dsm[4] * invB, m2r = dsm[5] * invB;
        double m1i = dsm[6] * invB, m2i = dsm[7] * invB;
        out[0] = (float)((SumA + 2.0 * m1r * SumBr + 2.0 * m1i * SumBi
                          + (m2r + m2i) * SumC) * invB);
        g_count = 0;   // self-reset for next graph replay
    }
}

extern "C" void kernel_launch(void* const* d_in, const int* in_sizes, int n_in,
                              void* d_out, int out_size)
{
    const float* dnn   = (const float*)d_in[0];
    const float* bv    = (const float*)d_in[1];
    const float* hv    = (const float*)d_in[2];
    const float* xr    = (const float*)d_in[3];
    const float* xi    = (const float*)d_in[4];
    const float* isr   = (const float*)d_in[5];
    const float* isi   = (const float*)d_in[6];
    const float* ich   = (const float*)d_in[7];
    const float* noise = (const float*)d_in[8];
    const float* prob  = (const float*)d_in[9];

    isi_fused_kernel<<<NBLK, NT>>>(dnn, bv, hv, xr, xi, isr, isi, ich,
                                   noise, prob, (float*)d_out);
}